// round 17
// baseline (speedup 1.0000x reference)
#include <cuda_runtime.h>
#include <cuda_fp16.h>
#include <math.h>
#include <stdint.h>

#define BB   256
#define TT   365
#define HH   512
#define DD   32
#define K3   1536
#define DS   27
#define NBLK 128
#define KTOT 544

// ---------------- persistent device state ----------------
// Weight staging: row P = nt*96 + g*32 + ul, k in [0,544) = [x(32) ; h(512)]
__device__ __align__(16) __half g_Wp[K3 * KTOT];
__device__ __align__(16) __half g_x[BB * TT * DD];
__device__ __align__(16) __half g_h[2][BB * HH];
__device__ unsigned g_grp_cnt[8 * 32];      // 128B stride per mt-group
__device__ unsigned g_grp_phase[8 * 32];

__device__ __forceinline__ float hsig(float x) {
    return fminf(fmaxf(0.2f * x + 0.5f, 0.0f), 1.0f);
}
__device__ __forceinline__ float ftanh(float x) {
    float t = __expf(-2.0f * fabsf(x));
    return copysignf(__fdividef(1.0f - t, 1.0f + t), x);
}
__device__ __forceinline__ uint32_t smem_u32(const void* p) {
    uint32_t a;
    asm("{ .reg .u64 t; cvta.to.shared.u64 t, %1; cvt.u32.u64 %0, t; }" : "=r"(a) : "l"(p));
    return a;
}

#define LDSM_X4(r0, r1, r2, r3, addr)                                          \
    asm volatile("ldmatrix.sync.aligned.m8n8.x4.shared.b16 {%0,%1,%2,%3}, [%4];" \
                 : "=r"(r0), "=r"(r1), "=r"(r2), "=r"(r3) : "r"(addr))
#define LDSM_X2(r0, r1, addr)                                                  \
    asm volatile("ldmatrix.sync.aligned.m8n8.x2.shared.b16 {%0,%1}, [%2];"     \
                 : "=r"(r0), "=r"(r1) : "r"(addr))

#define MMA_F16(d, a0, a1, a2, a3, b0, b1)                                     \
    asm volatile("mma.sync.aligned.m16n8k16.row.col.f32.f16.f16.f32 "          \
                 "{%0,%1,%2,%3}, {%4,%5,%6,%7}, {%8,%9}, {%0,%1,%2,%3};"       \
                 : "+f"((d)[0]), "+f"((d)[1]), "+f"((d)[2]), "+f"((d)[3])      \
                 : "r"(a0), "r"(a1), "r"(a2), "r"(a3), "r"(b0), "r"(b1))

#define CP_ASYNC16(dst, src) \
    asm volatile("cp.async.cg.shared.global [%0], [%1], 16;" \
                 :: "r"(dst), "l"(src))
#define CP_COMMIT() asm volatile("cp.async.commit_group;" ::: "memory")
#define CP_WAIT0()  asm volatile("cp.async.wait_group 0;" ::: "memory")
#define CP_WAIT1()  asm volatile("cp.async.wait_group 1;" ::: "memory")
#define CP_WAIT2()  asm volatile("cp.async.wait_group 2;" ::: "memory")

// ---------------- SMEM layout ----------------
#define BROW      1104            // 544*2 + 16B pad (conflict-free LDSM phases)
#define SM_B      0               // 96 rows x 1104B = 105984
#define SM_A      105984          // 4 chunk bufs x 4096 (64-k fp16, swizzled)
#define ABUF_SZ   4096
#define SM_RED    122368          // 2 regions x 12 x 128 floats = 12288
#define SMEM_TOTAL 134656

// ---------------- prep kernels ----------------
__global__ void reset_bar() {
    if (threadIdx.x < 8 * 32) {
        g_grp_cnt[threadIdx.x] = 0;
        g_grp_phase[threadIdx.x] = 0;
    }
}

__global__ void prep_weights(const float* __restrict__ Wx, const float* __restrict__ Wh) {
    int P = blockIdx.x;                 // P = nt*96 + g*32 + ul
    int nt = P / 96, rq = P - nt * 96;
    int g = rq >> 5, ul = rq & 31;
    int col = g * HH + nt * 32 + ul;
    for (int k = threadIdx.x; k < KTOT; k += blockDim.x) {
        float w = (k < DD) ? Wx[(size_t)k * K3 + col]
                           : Wh[(size_t)(k - DD) * K3 + col];
        g_Wp[(size_t)P * KTOT + k] = __float2half_rn(w);
    }
}

__global__ void prep_x(const float* __restrict__ x_dyn) {
    int i = blockIdx.x * blockDim.x + threadIdx.x;
    if (i >= BB * TT * DD) return;
    g_x[i] = __float2half_rn(x_dyn[i]);
}

// ---------------- split group barrier (16 CTAs per mt) ----------------
__device__ __forceinline__ void grp_arrive(int mt, unsigned round) {
    unsigned old;
    asm volatile("atom.add.acq_rel.gpu.global.u32 %0, [%1], 1;"
                 : "=r"(old) : "l"(&g_grp_cnt[mt * 32]) : "memory");
    if (old + 1u == round * 16u)
        asm volatile("st.release.gpu.global.u32 [%0], %1;"
                     :: "l"(&g_grp_phase[mt * 32]), "r"(round) : "memory");
}
__device__ __forceinline__ void grp_wait(int mt, unsigned round) {
    if (threadIdx.x == 0) {
        unsigned p;
        do {
            asm volatile("ld.acquire.gpu.global.u32 %0, [%1];"
                         : "=r"(p) : "l"(&g_grp_phase[mt * 32]) : "memory");
        } while (p < round);
    }
    __syncthreads();
}

// ---- fragment bank load for one 64-k chunk (this warp's 2 ks) ----
#define LDSM_BANK(FA, FB, Bu_, Bb_)                                            \
    LDSM_X4(FA[0], FA[1], FA[2], FA[3], (Bu_) + aof00);                        \
    LDSM_X4(FA[4], FA[5], FA[6], FA[7], (Bu_) + aof10);                        \
    LDSM_X4(FA[8], FA[9], FA[10], FA[11], (Bu_) + aof01);                      \
    LDSM_X4(FA[12], FA[13], FA[14], FA[15], (Bu_) + aof11);                    \
    LDSM_X4(FB[0], FB[1], FB[2], FB[3], bA + (Bb_));                           \
    LDSM_X2(FB[4], FB[5], bO + (Bb_));                                         \
    LDSM_X4(FB[6], FB[7], FB[8], FB[9], bA + (Bb_) + 32);                      \
    LDSM_X2(FB[10], FB[11], bO + (Bb_) + 32);

// ---- 12 fp16 MMAs on one bank (2 ks x 6) ----
#define MMA_BANK(FA, FB)                                                       \
    MMA_F16(acc[0][0], FA[0], FA[1], FA[2], FA[3], FB[0], FB[1]);              \
    MMA_F16(acc[0][1], FA[4], FA[5], FA[6], FA[7], FB[0], FB[1]);              \
    MMA_F16(acc[1][0], FA[0], FA[1], FA[2], FA[3], FB[2], FB[3]);              \
    MMA_F16(acc[1][1], FA[4], FA[5], FA[6], FA[7], FB[2], FB[3]);              \
    MMA_F16(acc[2][0], FA[0], FA[1], FA[2], FA[3], FB[4], FB[5]);              \
    MMA_F16(acc[2][1], FA[4], FA[5], FA[6], FA[7], FB[4], FB[5]);              \
    MMA_F16(acc[0][0], FA[8], FA[9], FA[10], FA[11], FB[6], FB[7]);            \
    MMA_F16(acc[0][1], FA[12], FA[13], FA[14], FA[15], FB[6], FB[7]);          \
    MMA_F16(acc[1][0], FA[8], FA[9], FA[10], FA[11], FB[8], FB[9]);            \
    MMA_F16(acc[1][1], FA[12], FA[13], FA[14], FA[15], FB[8], FB[9]);          \
    MMA_F16(acc[2][0], FA[8], FA[9], FA[10], FA[11], FB[10], FB[11]);          \
    MMA_F16(acc[2][1], FA[12], FA[13], FA[14], FA[15], FB[10], FB[11]);

// One pipeline iteration (J = 0..7):
// wait chunk J+1 landed -> sync -> issue chunk J+3 -> LDSM J+1 -> MMA J
#define STEP_ITER(J, FAc, FBc, FAn, FBn) do {                                  \
    if ((J) <= 6) { CP_WAIT1(); } else { CP_WAIT0(); }                         \
    __syncthreads();                                                           \
    if ((J) <= 5) {                                                            \
        CP_ASYNC16(s0 + SM_A + (uint32_t)(((J) + 3) & 3) * ABUF_SZ + dst_off,  \
                   hsrc + hrow + ((uint32_t)((blkbase + 2 * ((J) + 3)) & 15) << 5)); \
        CP_COMMIT();                                                           \
    }                                                                          \
    {                                                                          \
        const uint32_t Bu_ = s0 + SM_A + (uint32_t)(((J) + 1) & 3) * ABUF_SZ;  \
        const uint32_t Bb_ = 64u +                                             \
            ((uint32_t)((nt + 2 * ((J) + 1) + khalf - 1) & 15) << 6);          \
        LDSM_BANK(FAn, FBn, Bu_, Bb_)                                          \
    }                                                                          \
    MMA_BANK(FAc, FBc)                                                         \
} while (0)

// ---------------- persistent LSTM kernel ----------------
// 128 CTAs x 256 thr. CTA tile 32 rows x 32 units (96 z-cols).
// K = 9 chunks of 64; 4 chunk buffers + register double-buffered fragments;
// single-pass fp16. Symmetric epilogue: khalf0 owns rows 0-15, khalf1 rows
// 16-31; partials exchanged via smem; out-stores deferred past arrive.
__global__ __launch_bounds__(256, 1)
void lstm_persist(const float* __restrict__ x_static,
                  const float* __restrict__ sk,
                  const float* __restrict__ sb,
                  const float* __restrict__ bias,
                  float* __restrict__ out) {
    extern __shared__ char smem[];
    const uint32_t s0 = smem_u32(smem);
    const int tid = threadIdx.x;
    const int lane = tid & 31;
    const int wid = tid >> 5;
    const int nq = wid & 3;
    const int khalf = wid >> 2;
    const int mt = blockIdx.x & 7;
    const int nt = blockIdx.x >> 3;
    const int m0 = mt * 32;
    const int u0 = nt * 32;

    // ---- one-time: weights into SMEM ----
    for (int i = tid; i < 96 * 68; i += 256) {
        int pl = i / 68, c = i - pl * 68;
        size_t src = (size_t)(nt * 96 + pl) * KTOT + c * 8;
        *reinterpret_cast<uint4*>(smem + SM_B + pl * BROW + c * 16) =
            *reinterpret_cast<const uint4*>(&g_Wp[src]);
    }

    // ---- per-thread ownership: rows rowbase, rowbase+8 (mfrag = khalf) ----
    const int rowbase = m0 + khalf * 16 + (lane >> 2);
    const int uA = u0 + nq * 8 + (lane & 3) * 2;

    const float bf0 = bias[uA],          bf1 = bias[uA + 1];
    const float bg0 = bias[HH + uA],     bg1 = bias[HH + uA + 1];
    const float bo0 = bias[2 * HH + uA], bo1 = bias[2 * HH + uA + 1];

    float c_reg[4], ig_reg[4];
#pragma unroll
    for (int i = 0; i < 4; i++) c_reg[i] = 0.f;
#pragma unroll
    for (int i = 0; i < 2; i++) {
        int row = rowbase + i * 8;
#pragma unroll
        for (int jj = 0; jj < 2; jj++) {
            int u = uA + jj;
            float a = sb[u];
#pragma unroll
            for (int d = 0; d < DS; d++)
                a = fmaf(x_static[row * DS + d], sk[d * HH + u], a);
            ig_reg[i * 2 + jj] = hsig(a);
        }
        *reinterpret_cast<__half2*>(&g_h[0][row * HH + uA]) =
            __floats2half2_rn(0.f, 0.f);
    }

    // ---- hoisted loader constants (1 cp.async 16B per thread per chunk) ----
    const int rowl = tid >> 3;                  // 0..31
    const int subl = tid & 7;                   // 16B slot within 128B row
    const int sL = subl >> 2;                   // slab half within chunk
    const uint32_t dst_off = rowl * 128 + ((subl ^ (rowl & 7)) << 4);
    const size_t xsrc0 = (size_t)(m0 + rowl) * TT * DD + (subl & 3) * 8;
    const uint32_t hrow = (m0 + rowl) * HH + (subl & 3) * 8;      // + blk*32
    const int blkbase = nt + 15 + sL;           // chunk c: blk = (blkbase+2c)&15

    // ---- ldmatrix lane addresses ----
    uint32_t aof00, aof01, aof10, aof11;
    {
        const int r0 = lane & 15, r1 = 16 + (lane & 15);
        const int colh = lane >> 4;
        const int cb = khalf * 4 + colh;
#define AOFF(r, c) ((uint32_t)((r) * 128 + ((((c)) ^ ((r) & 7)) << 4)))
        aof00 = AOFF(r0, cb);     aof01 = AOFF(r0, cb + 2);
        aof10 = AOFF(r1, cb);     aof11 = AOFF(r1, cb + 2);
#undef AOFF
    }
    const int oct = lane >> 3, l8 = lane & 7;
    const uint32_t koff = (oct & 1) * 16;
    const int wq8 = nq * 8;
    const uint32_t bA = s0 + SM_B + ((oct < 2 ? wq8 : 32 + wq8) + l8) * BROW + koff;
    const uint32_t bO = s0 + SM_B + (64 + wq8 + (lane & 7)) * BROW
                      + (((lane & 15) >> 3) << 4);

    // prologue: h(0) visible within CTA, post arrival, issue chunk0 (x + own h)
    __syncthreads();
    if (tid == 0) grp_arrive(mt, 1u);
    {
        const __half* src0 = (sL == 0) ? (g_x + xsrc0)
                                       : (g_h[0] + hrow + ((uint32_t)nt << 5));
        CP_ASYNC16(s0 + SM_A + dst_off, src0);
        CP_COMMIT();
    }

    uint32_t fA0[16], fB0[12], fA1[16], fB1[12];

#pragma unroll 1
    for (int t = 0; t < TT; t++) {
        const int tpar = t & 1;
        const __half* __restrict__ hsrc = g_h[tpar];

        grp_wait(mt, (unsigned)t + 1u);   // all h(t) published group-wide

        // issue chunk1 and chunk2
        CP_ASYNC16(s0 + SM_A + 1 * ABUF_SZ + dst_off,
                   hsrc + hrow + ((uint32_t)((blkbase + 2) & 15) << 5));
        CP_COMMIT();
        CP_ASYNC16(s0 + SM_A + 2 * ABUF_SZ + dst_off,
                   hsrc + hrow + ((uint32_t)((blkbase + 4) & 15) << 5));
        CP_COMMIT();

        float acc[3][2][4];
#pragma unroll
        for (int g = 0; g < 3; g++)
#pragma unroll
            for (int mf = 0; mf < 2; mf++)
#pragma unroll
                for (int e2 = 0; e2 < 4; e2++) acc[g][mf][e2] = 0.f;

        // preload bank0 <- chunk0
        CP_WAIT2();
        __syncthreads();
        {
            const uint32_t Bb0 = khalf ? (64u + ((uint32_t)nt << 6)) : 0u;
            LDSM_BANK(fA0, fB0, s0 + SM_A, Bb0)
        }

        STEP_ITER(0, fA0, fB0, fA1, fB1);
        STEP_ITER(1, fA1, fB1, fA0, fB0);
        STEP_ITER(2, fA0, fB0, fA1, fB1);
        STEP_ITER(3, fA1, fB1, fA0, fB0);
        STEP_ITER(4, fA0, fB0, fA1, fB1);
        STEP_ITER(5, fA1, fB1, fA0, fB0);
        STEP_ITER(6, fA0, fB0, fA1, fB1);
        STEP_ITER(7, fA1, fB1, fA0, fB0);
        // chunk8: only lower half real (slab16); khalf1 skips
        if (khalf == 0) { MMA_BANK(fA0, fB0) }

        // ---- symmetric cross-warp k exchange ----
        // region mf0 (rows 0-15) written by khalf1; region mf1 by khalf0
        {
            float* base = reinterpret_cast<float*>(smem + SM_RED);
            float* wr = base + (khalf ^ 1) * 1536;
            const int s = nq * 32 + lane;
            const int wmf = khalf ^ 1;
#pragma unroll
            for (int g = 0; g < 3; g++)
#pragma unroll
                for (int e2 = 0; e2 < 4; e2++)
                    wr[(g * 4 + e2) * 128 + s] = acc[g][wmf][e2];
            __syncthreads();
            float* rd = base + khalf * 1536;
#pragma unroll
            for (int g = 0; g < 3; g++)
#pragma unroll
                for (int e2 = 0; e2 < 4; e2++)
                    acc[g][khalf][e2] += rd[(g * 4 + e2) * 128 + s];
        }

        // ---- gates on own mfrag (all 8 warps) ----
        __half* __restrict__ hdst = g_h[tpar ^ 1];
        float hv[4];
#pragma unroll
        for (int i = 0; i < 2; i++) {
            const int dp = i * 2;
            float zf0 = acc[0][khalf][dp + 0] + bf0, zf1 = acc[0][khalf][dp + 1] + bf1;
            float zg0 = acc[1][khalf][dp + 0] + bg0, zg1 = acc[1][khalf][dp + 1] + bg1;
            float zo0 = acc[2][khalf][dp + 0] + bo0, zo1 = acc[2][khalf][dp + 1] + bo1;
            float c0 = hsig(zf0) * c_reg[dp + 0] + ig_reg[dp + 0] * ftanh(zg0);
            float c1 = hsig(zf1) * c_reg[dp + 1] + ig_reg[dp + 1] * ftanh(zg1);
            c_reg[dp + 0] = c0;
            c_reg[dp + 1] = c1;
            float h0 = hsig(zo0) * ftanh(c0);
            float h1 = hsig(zo1) * ftanh(c1);
            hv[dp + 0] = h0;
            hv[dp + 1] = h1;
            int row = rowbase + i * 8;
            *reinterpret_cast<__half2*>(&hdst[row * HH + uA]) =
                __floats2half2_rn(h0, h1);
        }

        __syncthreads();                 // red reads + h(t+1) writes done CTA-wide
        if (tid == 0) grp_arrive(mt, (unsigned)t + 2u);   // publish h(t+1)

        // deferred out-stores (nobody consumes them; overlap next wait)
#pragma unroll
        for (int i = 0; i < 2; i++) {
            int row = rowbase + i * 8;
            float2 ov = make_float2(hv[i * 2], hv[i * 2 + 1]);
            *reinterpret_cast<float2*>(&out[(size_t)row * TT * HH + (size_t)t * HH + uA]) = ov;
        }

        if (t + 1 < TT) {                // issue next step's chunk0 (x + own h)
            const __half* src0 = (sL == 0)
                ? (g_x + xsrc0 + (size_t)(t + 1) * DD)
                : (g_h[(t + 1) & 1] + hrow + ((uint32_t)nt << 5));
            CP_ASYNC16(s0 + SM_A + dst_off, src0);
            CP_COMMIT();
        }
    }
}

// ---------------- launcher ----------------
extern "C" void kernel_launch(void* const* d_in, const int* in_sizes, int n_in,
                              void* d_out, int out_size) {
    const float* x_dyn    = (const float*)d_in[0];
    const float* x_static = (const float*)d_in[1];
    const float* Wx       = (const float*)d_in[2];
    const float* Wh       = (const float*)d_in[3];
    const float* bias     = (const float*)d_in[4];
    const float* sk       = (const float*)d_in[5];
    const float* sb       = (const float*)d_in[6];
    float* out = (float*)d_out;

    cudaFuncSetAttribute(lstm_persist, cudaFuncAttributeMaxDynamicSharedMemorySize, SMEM_TOTAL);

    reset_bar<<<1, 256>>>();
    prep_weights<<<K3, 128>>>(Wx, Wh);
    prep_x<<<(BB * TT * DD + 127) / 128, 128>>>(x_dyn);
    lstm_persist<<<NBLK, 256, SMEM_TOTAL>>>(x_static, sk, sb, bias, out);
}